// round 17
// baseline (speedup 1.0000x reference)
#include <cuda_runtime.h>
#include <cuda_fp16.h>
#include <stdint.h>

#define DEVINL __device__ __forceinline__

// ---------------------------------------------------------------------------
// Dims: z[N,64] -> h1[N,128] -> h2[N,128] -> b[N,12(pad16)]
// Single-pass fp16 (m16n8k16, fp32 accumulate). Each warp independently owns
// one 16-row warp-tile per loop step; z read by direct coalesced LDG (no smem
// staging), so block size is free: 320 threads -> 10 warps/SM (2.5/SMSP).
// ---------------------------------------------------------------------------

// fp16 weight pitches (elems / bytes); pitch mod 128B == 16 -> conflict-free
static constexpr int PZ  = 72;   static constexpr int PZB = 144;   // W1 k=64
static constexpr int PH  = 136;  static constexpr int PHB = 272;   // W2/W3 k=128

static constexpr unsigned OFF_W1 = 0;                      // [128][72] f16
static constexpr unsigned OFF_W2 = 18432;                  // [128][136] f16
static constexpr unsigned OFF_W3 = 53248;                  // [16][136] f16
static constexpr unsigned WB     = 57600;

static constexpr unsigned B1O = WB;                        // 128 f32
static constexpr unsigned B2O = B1O + 512;                 // 128 f32
static constexpr unsigned B3O = B2O + 512;                 // 16 f32
static constexpr unsigned SMT = B3O + 64;                  // 58688

static constexpr int NWARP = 10;                           // warps per CTA

__device__ __align__(16) unsigned char g_wb[WB];

// ---------------------------------------------------------------------------
DEVINL uint32_t smem_u32(const void* p) {
    uint32_t a;
    asm("{ .reg .u64 t; cvta.to.shared.u64 t, %1; cvt.u32.u64 %0, t; }" : "=r"(a) : "l"(p));
    return a;
}

#define LDSM4(R, ADDR) \
    asm volatile("ldmatrix.sync.aligned.m8n8.x4.shared.b16 {%0,%1,%2,%3},[%4];" \
                 : "=r"((R)[0]), "=r"((R)[1]), "=r"((R)[2]), "=r"((R)[3]) : "r"(ADDR))

// fp16 MMA, fp32 accumulate: D[16x8] += A[16x16] * B[16x8]
#define MMAH(C, A, B0, B1) \
    asm volatile("mma.sync.aligned.m16n8k16.row.col.f32.f16.f16.f32 " \
                 "{%0,%1,%2,%3},{%4,%5,%6,%7},{%8,%9},{%0,%1,%2,%3};" \
                 : "+f"((C)[0]), "+f"((C)[1]), "+f"((C)[2]), "+f"((C)[3]) \
                 : "r"((A)[0]), "r"((A)[1]), "r"((A)[2]), "r"((A)[3]), \
                   "r"(B0), "r"(B1))

DEVINL uint32_t pkh2(float a, float b) {
    __half2 h = __floats2half2_rn(a, b);
    return *reinterpret_cast<uint32_t*>(&h);
}

// ---------------------------------------------------------------------------
// prep: weights -> [n][k] fp16, padded pitch
// ---------------------------------------------------------------------------
__global__ void tastenet_prep(const float* __restrict__ W1,
                              const float* __restrict__ W2,
                              const float* __restrict__ W3) {
    int i = blockIdx.x * blockDim.x + threadIdx.x;
    __half* w1 = (__half*)(g_wb + OFF_W1);
    __half* w2 = (__half*)(g_wb + OFF_W2);
    __half* w3 = (__half*)(g_wb + OFF_W3);

    if (i < 128 * 64) {                       // W1 (64,128) -> [n][k]
        int n = i >> 6, k = i & 63;
        w1[n * PZ + k] = __float2half(W1[k * 128 + n]);
    }
    if (i < 128 * 128) {                      // W2 (128,128) -> [n][k]
        int n = i >> 7, k = i & 127;
        w2[n * PH + k] = __float2half(W2[k * 128 + n]);
    }
    if (i < 16 * 128) {                       // W3 (128,12) pad n to 16
        int n = i >> 7, k = i & 127;
        float w = (n < 12) ? W3[k * 12 + n] : 0.f;
        w3[n * PH + k] = __float2half(w);
    }
}

// ---------------------------------------------------------------------------
// main persistent kernel: 320 threads, each warp independently processes
// 16-row warp-tiles with a global stride. No intra-loop synchronization.
// ---------------------------------------------------------------------------
__global__ void __launch_bounds__(320, 1)
tastenet_main(const float* __restrict__ x, const float* __restrict__ z,
              const float* __restrict__ b1, const float* __restrict__ b2,
              const float* __restrict__ b3, float* __restrict__ out,
              int num_wt) {
    extern __shared__ __align__(16) unsigned char smem[];
    const int tid = threadIdx.x;

    // ---- one-time: copy weight image + biases into smem ----
    {
        const float4* s = reinterpret_cast<const float4*>(g_wb);
        float4* d = reinterpret_cast<float4*>(smem);
        for (int i = tid; i < (int)(WB / 16); i += 320) d[i] = s[i];
        float* sb1 = (float*)(smem + B1O);
        float* sb2 = (float*)(smem + B2O);
        float* sb3 = (float*)(smem + B3O);
        if (tid < 128) { sb1[tid] = b1[tid]; sb2[tid] = b2[tid]; }
        if (tid < 16)  sb3[tid] = (tid < 12) ? b3[tid] : 0.f;
    }
    __syncthreads();

    const uint32_t sb = smem_u32(smem);
    const int w = tid >> 5, l = tid & 31;
    const int g = l >> 2, q = l & 3;
    const int qq = l >> 3, rr = l & 7;

    // B-operand ldmatrix lane bases: rows n 0-7/8-15, k-halves 16B
    const int brow = ((qq >> 1) << 3) + rr;
    const int bkof = (qq & 1) << 4;
    const uint32_t bW1 = sb + OFF_W1 + brow * PZB + bkof;
    const uint32_t bW2 = sb + OFF_W2 + brow * PHB + bkof;
    const uint32_t bW3 = sb + OFF_W3 + brow * PHB + bkof;

    const float* sb3 = (const float*)(smem + B3O);
    const unsigned char* b1p = smem + B1O;
    const unsigned char* b2p = smem + B2O;

    const int wstride = NWARP * gridDim.x;

    for (int wt = blockIdx.x * NWARP + w; wt < num_wt; wt += wstride) {
        const int row0 = wt * 16 + g;

        // ---- build layer-1 A fragments straight from gmem z (coalesced) ----
        // lane quad covers one 32B sector: float2 at col 16kt+2q
        uint32_t A1[4][4];
        {
            const float2* z0 = reinterpret_cast<const float2*>(
                                   z + (size_t)row0 * 64) + q;
            const float2* z8 = z0 + 8 * 32;          // +8 rows (32 float2/row)
#pragma unroll
            for (int kt = 0; kt < 4; kt++) {
                float2 vl0 = z0[8 * kt];             // cols 16kt+2q,   +1
                float2 vl8 = z8[8 * kt];
                float2 vh0 = z0[8 * kt + 4];         // cols 16kt+2q+8, +9
                float2 vh8 = z8[8 * kt + 4];
                A1[kt][0] = pkh2(vl0.x, vl0.y);      // row g,   k-low
                A1[kt][1] = pkh2(vl8.x, vl8.y);      // row g+8, k-low
                A1[kt][2] = pkh2(vh0.x, vh0.y);      // row g,   k-high
                A1[kt][3] = pkh2(vh8.x, vh8.y);      // row g+8, k-high
            }
        }

        float acc[16][4];
#pragma unroll
        for (int n = 0; n < 16; n++)
#pragma unroll
            for (int c = 0; c < 4; c++) acc[n][c] = 0.f;

        // ---- layer 1: K=64 (4 k-tiles of 16) ----
#pragma unroll
        for (int kt = 0; kt < 4; kt++) {
#pragma unroll
            for (int np2 = 0; np2 < 8; np2++) {
                uint32_t B[4];
                LDSM4(B, bW1 + np2 * 16 * PZB + kt * 32);
                MMAH(acc[2 * np2],     A1[kt], B[0], B[1]);
                MMAH(acc[2 * np2 + 1], A1[kt], B[2], B[3]);
            }
        }

        // ---- h1 = relu(acc+b1) -> A2 fp16 frags (registers only) ----
        uint32_t A2[8][4];
#pragma unroll
        for (int j = 0; j < 8; j++) {
            float2 bA = *(const float2*)(b1p + (16 * j + 2 * q) * 4);
            float2 bB = *(const float2*)(b1p + (16 * j + 8 + 2 * q) * 4);
            float v0 = fmaxf(acc[2 * j][0] + bA.x, 0.f);
            float v1 = fmaxf(acc[2 * j][1] + bA.y, 0.f);
            float v2 = fmaxf(acc[2 * j][2] + bA.x, 0.f);
            float v3 = fmaxf(acc[2 * j][3] + bA.y, 0.f);
            float u0 = fmaxf(acc[2 * j + 1][0] + bB.x, 0.f);
            float u1 = fmaxf(acc[2 * j + 1][1] + bB.y, 0.f);
            float u2 = fmaxf(acc[2 * j + 1][2] + bB.x, 0.f);
            float u3 = fmaxf(acc[2 * j + 1][3] + bB.y, 0.f);
            A2[j][0] = pkh2(v0, v1);   // row g,   k-low
            A2[j][1] = pkh2(v2, v3);   // row g+8, k-low
            A2[j][2] = pkh2(u0, u1);   // row g,   k-high
            A2[j][3] = pkh2(u2, u3);   // row g+8, k-high
        }

#pragma unroll
        for (int n = 0; n < 16; n++)
#pragma unroll
            for (int c = 0; c < 4; c++) acc[n][c] = 0.f;

        // ---- layer 2: K=128 (8 k-tiles) ----
#pragma unroll
        for (int kt = 0; kt < 8; kt++) {
#pragma unroll
            for (int np2 = 0; np2 < 8; np2++) {
                uint32_t B[4];
                LDSM4(B, bW2 + np2 * 16 * PHB + kt * 32);
                MMAH(acc[2 * np2],     A2[kt], B[0], B[1]);
                MMAH(acc[2 * np2 + 1], A2[kt], B[2], B[3]);
            }
        }

        // ---- h2 = relu(acc+b2) -> A frags (reuse A2) ----
#pragma unroll
        for (int j = 0; j < 8; j++) {
            float2 bA = *(const float2*)(b2p + (16 * j + 2 * q) * 4);
            float2 bB = *(const float2*)(b2p + (16 * j + 8 + 2 * q) * 4);
            float v0 = fmaxf(acc[2 * j][0] + bA.x, 0.f);
            float v1 = fmaxf(acc[2 * j][1] + bA.y, 0.f);
            float v2 = fmaxf(acc[2 * j][2] + bA.x, 0.f);
            float v3 = fmaxf(acc[2 * j][3] + bA.y, 0.f);
            float u0 = fmaxf(acc[2 * j + 1][0] + bB.x, 0.f);
            float u1 = fmaxf(acc[2 * j + 1][1] + bB.y, 0.f);
            float u2 = fmaxf(acc[2 * j + 1][2] + bB.x, 0.f);
            float u3 = fmaxf(acc[2 * j + 1][3] + bB.y, 0.f);
            A2[j][0] = pkh2(v0, v1);
            A2[j][1] = pkh2(v2, v3);
            A2[j][2] = pkh2(u0, u1);
            A2[j][3] = pkh2(u2, u3);
        }

        // ---- layer 3: [128] -> 16, even/odd acc sets for dep distance ----
        float a3e[2][4], a3o[2][4];
#pragma unroll
        for (int n = 0; n < 2; n++)
#pragma unroll
            for (int c = 0; c < 4; c++) { a3e[n][c] = 0.f; a3o[n][c] = 0.f; }
#pragma unroll
        for (int kt = 0; kt < 8; kt++) {
            uint32_t B[4];
            LDSM4(B, bW3 + kt * 32);
            if (kt & 1) {
                MMAH(a3o[0], A2[kt], B[0], B[1]);
                MMAH(a3o[1], A2[kt], B[2], B[3]);
            } else {
                MMAH(a3e[0], A2[kt], B[0], B[1]);
                MMAH(a3e[1], A2[kt], B[2], B[3]);
            }
        }
        float a3[2][4];
#pragma unroll
        for (int n = 0; n < 2; n++)
#pragma unroll
            for (int c = 0; c < 4; c++) a3[n][c] = a3e[n][c] + a3o[n][c];

        // ---- epilogue: clamps, taste*x segment sums via quad shuffles ----
        {
            float b3A = sb3[2 * q], b3B = sb3[2 * q + 1];
            float b3C = sb3[8 + 2 * q], b3D = sb3[9 + 2 * q];
#pragma unroll
            for (int rs = 0; rs < 2; rs++) {
                float vA = a3[0][rs * 2 + 0] + b3A;   // col 2q
                float vB = a3[0][rs * 2 + 1] + b3B;   // col 2q+1
                float vC = a3[1][rs * 2 + 0] + b3C;   // col 8+2q
                float vD = a3[1][rs * 2 + 1] + b3D;   // col 9+2q
                if (q < 3)  vA = fminf(vA, 0.f);      // cols 0,2,4 clamp; col6 raw
                vB = fminf(vB, 0.f);                  // cols 1,3,5,7 clamp
                if (q == 0) vC = fminf(vC, 0.f);      // col 8 clamp

                int row = row0 + rs * 8;
                const float* xr = x + (size_t)row * 9;
                float l0 = xr[q];
                float l1 = xr[4 + q];
                float l2 = xr[8];

                unsigned basel = (unsigned)(l & ~3);
                float xAl = __shfl_sync(0xffffffffu, l0, basel | ((2 * q) & 3));
                float xAh = __shfl_sync(0xffffffffu, l1, basel | ((2 * q) & 3));
                float xBl = __shfl_sync(0xffffffffu, l0, basel | ((2 * q + 1) & 3));
                float xBh = __shfl_sync(0xffffffffu, l1, basel | ((2 * q + 1) & 3));
                float xA = (q < 2) ? xAl : xAh;
                float xB = (q < 2) ? xBl : xBh;

                float p0 = 0.f, p1 = 0.f, p2 = 0.f;
                if (q == 0) {
                    p0 = fmaf(xA, vA, xB * vB) + vD;  // x0*t0 + x1*t1 + i0
                    p2 = l2 * vC;                      // x8*t8
                } else if (q == 1) {
                    p0 = xA * vA;                      // x2*t2
                    p1 = xB * vB + vC;                 // x3*t3 + i1
                    p2 = vD;                           // i2
                } else if (q == 2) {
                    p1 = fmaf(xA, vA, xB * vB);        // x4*t4 + x5*t5
                } else {
                    p2 = fmaf(xA, vA, xB * vB);        // x6*t6 + x7*t7
                }
                p0 += __shfl_xor_sync(0xffffffffu, p0, 1);
                p0 += __shfl_xor_sync(0xffffffffu, p0, 2);
                p1 += __shfl_xor_sync(0xffffffffu, p1, 1);
                p1 += __shfl_xor_sync(0xffffffffu, p1, 2);
                p2 += __shfl_xor_sync(0xffffffffu, p2, 1);
                p2 += __shfl_xor_sync(0xffffffffu, p2, 2);
                if (q < 3) {
                    float val = (q == 0) ? p0 : (q == 1) ? p1 : p2;
                    out[(size_t)row * 3 + q] = val;
                }
            }
        }
    }
}

// ---------------------------------------------------------------------------
// kernel_launch
// ---------------------------------------------------------------------------
extern "C" void kernel_launch(void* const* d_in, const int* in_sizes, int n_in,
                              void* d_out, int out_size) {
    const float* x  = (const float*)d_in[0];
    const float* z  = (const float*)d_in[1];
    const float* W1 = (const float*)d_in[2];
    const float* b1 = (const float*)d_in[3];
    const float* W2 = (const float*)d_in[4];
    const float* b2 = (const float*)d_in[5];
    const float* W3 = (const float*)d_in[6];
    const float* b3 = (const float*)d_in[7];
    float* out = (float*)d_out;

    const int n = in_sizes[1] / 64;
    const int num_wt = n / 16;               // 16-row warp-tiles

    tastenet_prep<<<64, 256>>>(W1, W2, W3);

    static int smem_set = 0;
    if (!smem_set) {
        cudaFuncSetAttribute(tastenet_main,
                             cudaFuncAttributeMaxDynamicSharedMemorySize, SMT);
        smem_set = 1;
    }
    int dev = 0, sms = 148;
    cudaGetDevice(&dev);
    cudaDeviceGetAttribute(&sms, cudaDevAttrMultiProcessorCount, dev);
    int grid = sms;
    int maxg = (num_wt + NWARP - 1) / NWARP;
    if (grid > maxg) grid = maxg;
    if (grid < 1) grid = 1;

    tastenet_main<<<grid, 32 * NWARP, SMT>>>(x, z, b1, b2, b3, out, num_wt);
}